// round 4
// baseline (speedup 1.0000x reference)
#include <cuda_runtime.h>
#include <math.h>

#define BB 4
#define CC 3
#define HH 1024
#define WW 1024
#define NBC 12          // B*C
#define G0 255
#define G1 127
#define G2 63
#define G3 31

typedef unsigned long long ull;

// ---------------- f32x2 helpers ----------------
__device__ __forceinline__ ull pack2(float lo, float hi) {
    ull r; asm("mov.b64 %0, {%1,%2};" : "=l"(r) : "f"(lo), "f"(hi)); return r;
}
__device__ __forceinline__ float2 unpack2(ull v) {
    float2 r; asm("mov.b64 {%0,%1}, %2;" : "=f"(r.x), "=f"(r.y) : "l"(v)); return r;
}
__device__ __forceinline__ ull fma2(ull a, ull b, ull c) {
    ull d; asm("fma.rn.f32x2 %0, %1, %2, %3;" : "=l"(d) : "l"(a), "l"(b), "l"(c)); return d;
}
__device__ __forceinline__ ull add2(ull a, ull b) {
    ull d; asm("add.rn.f32x2 %0, %1, %2;" : "=l"(d) : "l"(a), "l"(b)); return d;
}
__device__ __forceinline__ ull relu2(ull v) {
    float2 t = unpack2(v);
    return pack2(fmaxf(t.x, 0.f), fmaxf(t.y, 0.f));
}

// ---------------- scratch ----------------
__device__ float dS0[4][NBC*G0*G0];   // level-0 box sums: Sg, Ss, Sgg, Sgs
__device__ float dS1[4][NBC*G1*G1];
__device__ float dS2[4][NBC*G2*G2];
__device__ float dF1[2][NBC*G1*G1];
__device__ float dF2[2][NBC*G2*G2];
__device__ float dF3[2][NBC*G3*G3];
__device__ float dAf[NBC*G0*G0];      // A
__device__ float dCf[NBC*G0*G0];      // b = my1 - A*mx1

// ---------------- kernel 1: level-0 box sums (r=8, s=4, VALID) ----------------
__global__ __launch_bounds__(256) void boxsum_kernel(const float* __restrict__ guide,
                                                     const float* __restrict__ src) {
    __shared__ __align__(16) float shg[4 * 1024];
    __shared__ __align__(16) float shs[4 * 1024];
    const int t  = threadIdx.x;
    const int bc = blockIdx.y;
    const int i0 = blockIdx.x * 8;
    const int i1 = min(i0 + 8, 255);

    const float* gbase = guide + (size_t)bc * HH * WW;
    const float* sbase = src   + (size_t)bc * HH * WW;

    float qg = 0.f, qs = 0.f, qgg = 0.f, qgs = 0.f;

    for (int m = i0; m <= i1; ++m) {
        const float4* gp = (const float4*)(gbase + (size_t)(4 * m) * WW);
        const float4* sp = (const float4*)(sbase + (size_t)(4 * m) * WW);
        float4* shg4 = (float4*)shg;
        float4* shs4 = (float4*)shs;
        #pragma unroll
        for (int k = 0; k < 4; ++k) {
            int idx = t + k * 256;
            shg4[idx] = gp[idx];
            shs4[idx] = sp[idx];
        }
        __syncthreads();

        if (t < 255) {
            float pg = 0.f, ps = 0.f, pgg = 0.f, pgs = 0.f;
            #pragma unroll
            for (int rr = 0; rr < 4; ++rr) {
                const float* g = shg + rr * 1024 + 4 * t;
                const float* s = shs + rr * 1024 + 4 * t;
                float4 ga = *(const float4*)(g);
                float4 gb = *(const float4*)(g + 4);
                float4 sa = *(const float4*)(s);
                float4 sb = *(const float4*)(s + 4);
                float gv[8] = {ga.x, ga.y, ga.z, ga.w, gb.x, gb.y, gb.z, gb.w};
                float sv[8] = {sa.x, sa.y, sa.z, sa.w, sb.x, sb.y, sb.z, sb.w};
                #pragma unroll
                for (int k = 0; k < 8; ++k) {
                    pg += gv[k];
                    ps += sv[k];
                    pgg = fmaf(gv[k], gv[k], pgg);
                    pgs = fmaf(gv[k], sv[k], pgs);
                }
            }
            if (m > i0) {
                int off = bc * G0 * G0 + (m - 1) * G0 + t;
                dS0[0][off] = qg + pg;
                dS0[1][off] = qs + ps;
                dS0[2][off] = qgg + pgg;
                dS0[3][off] = qgs + pgs;
            }
            qg = pg; qs = ps; qgg = pgg; qgs = pgs;
        }
        __syncthreads();
    }
}

// ---------------- pyramid ----------------
__device__ __forceinline__ void pyr_step(const float* __restrict__ in0, const float* __restrict__ in1,
                                         const float* __restrict__ in2, const float* __restrict__ in3,
                                         float* s0, float* s1, float* s2, float* s3,
                                         float* fcov, float* fvar,
                                         int GIN, int GOUT, float INVN, int bc, int idx) {
    int i = idx / GOUT, j = idx - i * GOUT;
    int p00 = bc * GIN * GIN + 2 * i * GIN + 2 * j;
    #define SUM4(p) ((p)[p00] + (p)[p00 + 2] + (p)[p00 + 2*GIN] + (p)[p00 + 2*GIN + 2])
    float sg  = SUM4(in0);
    float ss  = SUM4(in1);
    float sgg = SUM4(in2);
    float sgs = SUM4(in3);
    #undef SUM4
    int o = bc * GOUT * GOUT + idx;
    if (s0) { s0[o] = sg; s1[o] = ss; s2[o] = sgg; s3[o] = sgs; }
    float mx = sg * INVN, my = ss * INVN;
    fcov[o] = fmaf(-mx, my, sgs * INVN);
    fvar[o] = fmaf(-mx, mx, sgg * INVN);
}

__global__ __launch_bounds__(256) void pyr1_kernel() {
    int idx = blockIdx.x * blockDim.x + threadIdx.x;
    if (idx >= G1 * G1) return;
    pyr_step(dS0[0], dS0[1], dS0[2], dS0[3],
             dS1[0], dS1[1], dS1[2], dS1[3],
             dF1[0], dF1[1], G0, G1, 1.f/256.f, blockIdx.y, idx);
}

__global__ __launch_bounds__(256) void pyr23_kernel() {
    const int bc = blockIdx.x;
    for (int idx = threadIdx.x; idx < G2 * G2; idx += 256)
        pyr_step(dS1[0], dS1[1], dS1[2], dS1[3],
                 dS2[0], dS2[1], dS2[2], dS2[3],
                 dF2[0], dF2[1], G1, G2, 1.f/1024.f, bc, idx);
    __syncthreads();
    for (int idx = threadIdx.x; idx < G3 * G3; idx += 256)
        pyr_step(dS2[0], dS2[1], dS2[2], dS2[3],
                 (float*)0, (float*)0, (float*)0, (float*)0,
                 dF3[0], dF3[1], G2, G3, 1.f/4096.f, bc, idx);
}

// ---------------- bilinear ----------------
__device__ __forceinline__ float bilin(const float* __restrict__ p, int base, int G,
                                       float wx, float wy) {
    float v00 = p[base],     v01 = p[base + 1];
    float v10 = p[base + G], v11 = p[base + G + 1];
    float v0 = v00 + wx * (v01 - v00);
    float v1 = v10 + wx * (v11 - v10);
    return v0 + wy * (v1 - v0);
}

__device__ __forceinline__ void sampleLevel(const float* __restrict__ covP,
                                            const float* __restrict__ varP,
                                            int G, int b, int i, int j, float* xo) {
    float scale = (float)((double)(G - 1) / 254.0);
    float py = i * scale, px = j * scale;
    int iy = (int)py; if (iy > G - 2) iy = G - 2;
    int ix = (int)px; if (ix > G - 2) ix = G - 2;
    float wy = py - iy, wx = px - ix;
    #pragma unroll
    for (int c = 0; c < 3; ++c) {
        int base = ((b * 3 + c) * G + iy) * G + ix;
        xo[c]     = bilin(covP, base, G, wx, wy);
        xo[3 + c] = bilin(varP, base, G, wx, wy);
    }
}

// ---------------- kernel 3: fused featbuild + tiled GEMM MLP ----------------
// Block: 256 threads, tile = 256 pixels (one row i of one batch) x 48 outputs.
// Thread tile: 8 pixels x 6 outputs, f32x2-packed over pixel pairs.
// smem layout (bytes):
//   x_s   [24][260] f  @ 0       (24960)
//   h_s   [48][260] f  @ 24960   (49920)
//   w1d   [24][48] ull @ 74880   (9216)
//   w2d   [48][48] ull @ 84096   (18432)
//   w3d   [3][48]  ull @ 102528  (1152)
//   b1d   [48]     ull @ 103680  (384)
//   b2d   [48]     ull @ 104064  (384)
#define GEMM_SMEM 104448
#define XS_STRIDE 260

__global__ __launch_bounds__(256, 2) void gemm_kernel(
    const float* __restrict__ w1, const float* __restrict__ g1, const float* __restrict__ b1,
    const float* __restrict__ rm1, const float* __restrict__ rv1,
    const float* __restrict__ w2, const float* __restrict__ g2, const float* __restrict__ b2,
    const float* __restrict__ rm2, const float* __restrict__ rv2,
    const float* __restrict__ w3) {

    extern __shared__ __align__(16) char smem_raw[];
    float* x_s = (float*)smem_raw;
    float* h_s = (float*)(smem_raw + 24960);
    ull* w1d = (ull*)(smem_raw + 74880);
    ull* w2d = (ull*)(smem_raw + 84096);
    ull* w3d = (ull*)(smem_raw + 102528);
    ull* b1d = (ull*)(smem_raw + 103680);
    ull* b2d = (ull*)(smem_raw + 104064);

    const int t = threadIdx.x;
    const int i = blockIdx.x;   // row
    const int b = blockIdx.y;   // batch

    // ---- weight prep (folded BN, duplicated), spread over all 256 threads ----
    // w1: 48x24, one thread per output row pair? use: threads 0..255 cover 1152 elems stride 256
    for (int e = t; e < 48 * 24; e += 256) {
        int o = e / 24, c = e - o * 24;
        float inv1 = g1[o] * rsqrtf(rv1[o] + 1e-5f);
        float w = w1[e] * inv1;
        w1d[c * 48 + o] = pack2(w, w);
    }
    for (int e = t; e < 48 * 48; e += 256) {
        int o = e / 48, c = e - o * 48;
        float inv2 = g2[o] * rsqrtf(rv2[o] + 1e-5f);
        float w = w2[e] * inv2;
        w2d[c * 48 + o] = pack2(w, w);
    }
    if (t < 48) {
        float inv1 = g1[t] * rsqrtf(rv1[t] + 1e-5f);
        float bb1 = fmaf(-rm1[t], inv1, b1[t]);
        b1d[t] = pack2(bb1, bb1);
        float inv2 = g2[t] * rsqrtf(rv2[t] + 1e-5f);
        float bb2 = fmaf(-rm2[t], inv2, b2[t]);
        b2d[t] = pack2(bb2, bb2);
        #pragma unroll
        for (int cc = 0; cc < 3; ++cc) {
            float w = w3[cc * 48 + t];
            w3d[cc * 48 + t] = pack2(w, w);
        }
    }

    // ---- feature build phase: thread t = pixel (i, j=t) ----
    {
        float x[24];
        if (t < 255) {
            const int j = t;
            #pragma unroll
            for (int c = 0; c < 3; ++c) {
                int off = (b * 3 + c) * G0 * G0 + i * G0 + j;
                float sg  = dS0[0][off] * (1.f/64.f);
                float ss  = dS0[1][off] * (1.f/64.f);
                float sgg = dS0[2][off] * (1.f/64.f);
                float sgs = dS0[3][off] * (1.f/64.f);
                x[c]     = fmaf(-sg, ss, sgs);
                x[3 + c] = fmaf(-sg, sg, sgg);
            }
            sampleLevel(dF1[0], dF1[1], G1, b, i, j, &x[6]);
            sampleLevel(dF2[0], dF2[1], G2, b, i, j, &x[12]);
            sampleLevel(dF3[0], dF3[1], G3, b, i, j, &x[18]);
        } else {
            #pragma unroll
            for (int f = 0; f < 24; ++f) x[f] = 0.f;
        }
        #pragma unroll
        for (int f = 0; f < 24; ++f)
            x_s[f * XS_STRIDE + t] = x[f];
    }
    __syncthreads();

    const int og = t & 7;          // output group
    const int pg = t >> 3;         // pixel group (0..31)
    const int o0 = og * 6;
    const int p0 = pg * 8;

    // ---- layer 1: 24 -> 48 ----
    ull acc[24];                    // [k][q] : 6 outputs x 4 pixel-pairs
    #pragma unroll
    for (int k = 0; k < 6; ++k) {
        ull bias = b1d[o0 + k];
        acc[k*4+0] = bias; acc[k*4+1] = bias; acc[k*4+2] = bias; acc[k*4+3] = bias;
    }
    #pragma unroll
    for (int c = 0; c < 24; ++c) {
        const ulonglong2* xr = (const ulonglong2*)&x_s[c * XS_STRIDE + p0];
        ulonglong2 xa = xr[0];
        ulonglong2 xb = xr[1];
        const ulonglong2* wr = (const ulonglong2*)&w1d[c * 48 + o0];
        ulonglong2 w01 = wr[0], w23 = wr[1], w45 = wr[2];
        ull wv[6] = {w01.x, w01.y, w23.x, w23.y, w45.x, w45.y};
        #pragma unroll
        for (int k = 0; k < 6; ++k) {
            acc[k*4+0] = fma2(wv[k], xa.x, acc[k*4+0]);
            acc[k*4+1] = fma2(wv[k], xa.y, acc[k*4+1]);
            acc[k*4+2] = fma2(wv[k], xb.x, acc[k*4+2]);
            acc[k*4+3] = fma2(wv[k], xb.y, acc[k*4+3]);
        }
    }
    // relu + store h
    #pragma unroll
    for (int k = 0; k < 6; ++k) {
        int o = o0 + k;
        ulonglong2* hp = (ulonglong2*)&h_s[o * XS_STRIDE + p0];
        ulonglong2 v0; v0.x = relu2(acc[k*4+0]); v0.y = relu2(acc[k*4+1]);
        ulonglong2 v1; v1.x = relu2(acc[k*4+2]); v1.y = relu2(acc[k*4+3]);
        hp[0] = v0; hp[1] = v1;
    }
    __syncthreads();

    // ---- layer 2: 48 -> 48 ----
    #pragma unroll
    for (int k = 0; k < 6; ++k) {
        ull bias = b2d[o0 + k];
        acc[k*4+0] = bias; acc[k*4+1] = bias; acc[k*4+2] = bias; acc[k*4+3] = bias;
    }
    #pragma unroll
    for (int c = 0; c < 48; ++c) {
        const ulonglong2* xr = (const ulonglong2*)&h_s[c * XS_STRIDE + p0];
        ulonglong2 xa = xr[0];
        ulonglong2 xb = xr[1];
        const ulonglong2* wr = (const ulonglong2*)&w2d[c * 48 + o0];
        ulonglong2 w01 = wr[0], w23 = wr[1], w45 = wr[2];
        ull wv[6] = {w01.x, w01.y, w23.x, w23.y, w45.x, w45.y};
        #pragma unroll
        for (int k = 0; k < 6; ++k) {
            acc[k*4+0] = fma2(wv[k], xa.x, acc[k*4+0]);
            acc[k*4+1] = fma2(wv[k], xa.y, acc[k*4+1]);
            acc[k*4+2] = fma2(wv[k], xb.x, acc[k*4+2]);
            acc[k*4+3] = fma2(wv[k], xb.y, acc[k*4+3]);
        }
    }
    // ---- layer 3 folded: relu(h2) -> 3 accumulators ----
    ull a3[12];                    // [cc][q]
    #pragma unroll
    for (int m = 0; m < 12; ++m) a3[m] = 0ull;
    #pragma unroll
    for (int k = 0; k < 6; ++k) {
        ull r0 = relu2(acc[k*4+0]);
        ull r1 = relu2(acc[k*4+1]);
        ull r2 = relu2(acc[k*4+2]);
        ull r3 = relu2(acc[k*4+3]);
        #pragma unroll
        for (int cc = 0; cc < 3; ++cc) {
            ull w = w3d[cc * 48 + o0 + k];
            a3[cc*4+0] = fma2(w, r0, a3[cc*4+0]);
            a3[cc*4+1] = fma2(w, r1, a3[cc*4+1]);
            a3[cc*4+2] = fma2(w, r2, a3[cc*4+2]);
            a3[cc*4+3] = fma2(w, r3, a3[cc*4+3]);
        }
    }
    // ---- reduce over the 8 output groups (consecutive lanes) ----
    #pragma unroll
    for (int m = 0; m < 12; ++m) {
        a3[m] = add2(a3[m], __shfl_xor_sync(0xffffffffu, a3[m], 1));
        a3[m] = add2(a3[m], __shfl_xor_sync(0xffffffffu, a3[m], 2));
        a3[m] = add2(a3[m], __shfl_xor_sync(0xffffffffu, a3[m], 4));
    }
    // ---- epilogue: lanes with og==0 write A and b ----
    if (og == 0) {
        #pragma unroll
        for (int cc = 0; cc < 3; ++cc) {
            int plane = (b * 3 + cc) * G0 * G0 + i * G0;
            #pragma unroll
            for (int q = 0; q < 4; ++q) {
                float2 A = unpack2(a3[cc*4+q]);
                int j0 = p0 + 2 * q;
                {
                    float mx = dS0[0][plane + j0] * (1.f/64.f);
                    float my = dS0[1][plane + j0] * (1.f/64.f);
                    dAf[plane + j0] = A.x;
                    dCf[plane + j0] = fmaf(-A.x, mx, my);
                }
                if (j0 + 1 < G0) {
                    float mx = dS0[0][plane + j0 + 1] * (1.f/64.f);
                    float my = dS0[1][plane + j0 + 1] * (1.f/64.f);
                    dAf[plane + j0 + 1] = A.y;
                    dCf[plane + j0 + 1] = fmaf(-A.y, mx, my);
                }
            }
        }
    }
}

// ---------------- kernel 4: upsample A,b + affine ----------------
__global__ __launch_bounds__(256) void final_kernel(const float* __restrict__ guide,
                                                    float* __restrict__ out) {
    __shared__ float sA[256];
    __shared__ float sC[256];
    const int y  = blockIdx.x;
    const int bc = blockIdx.y;
    const int t  = threadIdx.x;
    const float scale = (float)(254.0 / 1023.0);

    float py = y * scale;
    int iy = (int)py; if (iy > 253) iy = 253;
    float wy = py - iy;

    if (t < 255) {
        int b0 = bc * G0 * G0 + iy * G0 + t;
        float a0 = dAf[b0], a1 = dAf[b0 + G0];
        sA[t] = a0 + wy * (a1 - a0);
        float c0 = dCf[b0], c1 = dCf[b0 + G0];
        sC[t] = c0 + wy * (c1 - c0);
    }
    __syncthreads();

    size_t rowoff = ((size_t)bc * HH + y) * WW;
    float4 g = ((const float4*)(guide + rowoff))[t];
    float gv[4] = {g.x, g.y, g.z, g.w};
    float rv[4];
    #pragma unroll
    for (int k = 0; k < 4; ++k) {
        int xpix = 4 * t + k;
        float px = xpix * scale;
        int ix = (int)px; if (ix > 253) ix = 253;
        float wx = px - ix;
        float Av = sA[ix] + wx * (sA[ix + 1] - sA[ix]);
        float Cv = sC[ix] + wx * (sC[ix + 1] - sC[ix]);
        rv[k] = fmaf(Av, gv[k], Cv);
    }
    float4 r = {rv[0], rv[1], rv[2], rv[3]};
    ((float4*)(out + rowoff))[t] = r;
}

// ---------------- launch ----------------
extern "C" void kernel_launch(void* const* d_in, const int* in_sizes, int n_in,
                              void* d_out, int out_size) {
    const float* guide = (const float*)d_in[0];
    const float* src   = (const float*)d_in[1];
    const float* w1  = (const float*)d_in[2];
    const float* g1  = (const float*)d_in[3];
    const float* b1  = (const float*)d_in[4];
    const float* rm1 = (const float*)d_in[5];
    const float* rv1 = (const float*)d_in[6];
    const float* w2  = (const float*)d_in[7];
    const float* g2  = (const float*)d_in[8];
    const float* b2  = (const float*)d_in[9];
    const float* rm2 = (const float*)d_in[10];
    const float* rv2 = (const float*)d_in[11];
    const float* w3  = (const float*)d_in[12];
    float* out = (float*)d_out;

    cudaFuncSetAttribute(gemm_kernel, cudaFuncAttributeMaxDynamicSharedMemorySize, GEMM_SMEM);

    boxsum_kernel<<<dim3(32, NBC), 256>>>(guide, src);
    pyr1_kernel<<<dim3((G1*G1 + 255) / 256, NBC), 256>>>();
    pyr23_kernel<<<NBC, 256>>>();
    gemm_kernel<<<dim3(G0, BB), 256, GEMM_SMEM>>>(w1, g1, b1, rm1, rv1, w2, g2, b2, rm2, rv2, w3);
    final_kernel<<<dim3(HH, NBC), 256>>>(guide, out);
}

// round 5
// speedup vs baseline: 1.0311x; 1.0311x over previous
#include <cuda_runtime.h>
#include <math.h>

#define BB 4
#define CC 3
#define HH 1024
#define WW 1024
#define NBC 12          // B*C
#define G0 255
#define G1 127
#define G2 63
#define G3 31

typedef unsigned long long ull;

// ---------------- f32x2 helpers ----------------
__device__ __forceinline__ ull pack2(float lo, float hi) {
    ull r; asm("mov.b64 %0, {%1,%2};" : "=l"(r) : "f"(lo), "f"(hi)); return r;
}
__device__ __forceinline__ float2 unpack2(ull v) {
    float2 r; asm("mov.b64 {%0,%1}, %2;" : "=f"(r.x), "=f"(r.y) : "l"(v)); return r;
}
__device__ __forceinline__ ull fma2(ull a, ull b, ull c) {
    ull d; asm("fma.rn.f32x2 %0, %1, %2, %3;" : "=l"(d) : "l"(a), "l"(b), "l"(c)); return d;
}
__device__ __forceinline__ ull add2(ull a, ull b) {
    ull d; asm("add.rn.f32x2 %0, %1, %2;" : "=l"(d) : "l"(a), "l"(b)); return d;
}
__device__ __forceinline__ ull relu2(ull v) {
    float2 t = unpack2(v);
    return pack2(fmaxf(t.x, 0.f), fmaxf(t.y, 0.f));
}

// ---------------- scratch ----------------
__device__ float dS0[4][NBC*G0*G0];   // level-0 box sums: Sg, Ss, Sgg, Sgs
__device__ float dS1[4][NBC*G1*G1];
__device__ float dS2[4][NBC*G2*G2];
__device__ float dF1[2][NBC*G1*G1];
__device__ float dF2[2][NBC*G2*G2];
__device__ float dF3[2][NBC*G3*G3];
__device__ float dAf[NBC*G0*G0];      // A
__device__ float dCf[NBC*G0*G0];      // b = my1 - A*mx1

// ---------------- kernel 1: level-0 box sums (r=8, s=4, VALID) ----------------
__global__ __launch_bounds__(256) void boxsum_kernel(const float* __restrict__ guide,
                                                     const float* __restrict__ src) {
    __shared__ __align__(16) float shg[4 * 1024];
    __shared__ __align__(16) float shs[4 * 1024];
    const int t  = threadIdx.x;
    const int bc = blockIdx.y;
    const int i0 = blockIdx.x * 8;
    const int i1 = min(i0 + 8, 255);

    const float* gbase = guide + (size_t)bc * HH * WW;
    const float* sbase = src   + (size_t)bc * HH * WW;

    float qg = 0.f, qs = 0.f, qgg = 0.f, qgs = 0.f;

    for (int m = i0; m <= i1; ++m) {
        const float4* gp = (const float4*)(gbase + (size_t)(4 * m) * WW);
        const float4* sp = (const float4*)(sbase + (size_t)(4 * m) * WW);
        float4* shg4 = (float4*)shg;
        float4* shs4 = (float4*)shs;
        #pragma unroll
        for (int k = 0; k < 4; ++k) {
            int idx = t + k * 256;
            shg4[idx] = gp[idx];
            shs4[idx] = sp[idx];
        }
        __syncthreads();

        if (t < 255) {
            float pg = 0.f, ps = 0.f, pgg = 0.f, pgs = 0.f;
            #pragma unroll
            for (int rr = 0; rr < 4; ++rr) {
                const float* g = shg + rr * 1024 + 4 * t;
                const float* s = shs + rr * 1024 + 4 * t;
                float4 ga = *(const float4*)(g);
                float4 gb = *(const float4*)(g + 4);
                float4 sa = *(const float4*)(s);
                float4 sb = *(const float4*)(s + 4);
                float gv[8] = {ga.x, ga.y, ga.z, ga.w, gb.x, gb.y, gb.z, gb.w};
                float sv[8] = {sa.x, sa.y, sa.z, sa.w, sb.x, sb.y, sb.z, sb.w};
                #pragma unroll
                for (int k = 0; k < 8; ++k) {
                    pg += gv[k];
                    ps += sv[k];
                    pgg = fmaf(gv[k], gv[k], pgg);
                    pgs = fmaf(gv[k], sv[k], pgs);
                }
            }
            if (m > i0) {
                int off = bc * G0 * G0 + (m - 1) * G0 + t;
                dS0[0][off] = qg + pg;
                dS0[1][off] = qs + ps;
                dS0[2][off] = qgg + pgg;
                dS0[3][off] = qgs + pgs;
            }
            qg = pg; qs = ps; qgg = pgg; qgs = pgs;
        }
        __syncthreads();
    }
}

// ---------------- pyramid ----------------
__device__ __forceinline__ void pyr_step(const float* __restrict__ in0, const float* __restrict__ in1,
                                         const float* __restrict__ in2, const float* __restrict__ in3,
                                         float* s0, float* s1, float* s2, float* s3,
                                         float* fcov, float* fvar,
                                         int GIN, int GOUT, float INVN, int bc, int idx) {
    int i = idx / GOUT, j = idx - i * GOUT;
    int p00 = bc * GIN * GIN + 2 * i * GIN + 2 * j;
    #define SUM4(p) ((p)[p00] + (p)[p00 + 2] + (p)[p00 + 2*GIN] + (p)[p00 + 2*GIN + 2])
    float sg  = SUM4(in0);
    float ss  = SUM4(in1);
    float sgg = SUM4(in2);
    float sgs = SUM4(in3);
    #undef SUM4
    int o = bc * GOUT * GOUT + idx;
    if (s0) { s0[o] = sg; s1[o] = ss; s2[o] = sgg; s3[o] = sgs; }
    float mx = sg * INVN, my = ss * INVN;
    fcov[o] = fmaf(-mx, my, sgs * INVN);
    fvar[o] = fmaf(-mx, mx, sgg * INVN);
}

__global__ __launch_bounds__(256) void pyr1_kernel() {
    int idx = blockIdx.x * blockDim.x + threadIdx.x;
    if (idx >= G1 * G1) return;
    pyr_step(dS0[0], dS0[1], dS0[2], dS0[3],
             dS1[0], dS1[1], dS1[2], dS1[3],
             dF1[0], dF1[1], G0, G1, 1.f/256.f, blockIdx.y, idx);
}

__global__ __launch_bounds__(256) void pyr23_kernel() {
    const int bc = blockIdx.x;
    for (int idx = threadIdx.x; idx < G2 * G2; idx += 256)
        pyr_step(dS1[0], dS1[1], dS1[2], dS1[3],
                 dS2[0], dS2[1], dS2[2], dS2[3],
                 dF2[0], dF2[1], G1, G2, 1.f/1024.f, bc, idx);
    __syncthreads();
    for (int idx = threadIdx.x; idx < G3 * G3; idx += 256)
        pyr_step(dS2[0], dS2[1], dS2[2], dS2[3],
                 (float*)0, (float*)0, (float*)0, (float*)0,
                 dF3[0], dF3[1], G2, G3, 1.f/4096.f, bc, idx);
}

// ---------------- bilinear ----------------
__device__ __forceinline__ float bilin(const float* __restrict__ p, int base, int G,
                                       float wx, float wy) {
    float v00 = p[base],     v01 = p[base + 1];
    float v10 = p[base + G], v11 = p[base + G + 1];
    float v0 = v00 + wx * (v01 - v00);
    float v1 = v10 + wx * (v11 - v10);
    return v0 + wy * (v1 - v0);
}

__device__ __forceinline__ void sampleLevel(const float* __restrict__ covP,
                                            const float* __restrict__ varP,
                                            int G, int b, int i, int j, float* xo) {
    float scale = (float)((double)(G - 1) / 254.0);
    float py = i * scale, px = j * scale;
    int iy = (int)py; if (iy > G - 2) iy = G - 2;
    int ix = (int)px; if (ix > G - 2) ix = G - 2;
    float wy = py - iy, wx = px - ix;
    #pragma unroll
    for (int c = 0; c < 3; ++c) {
        int base = ((b * 3 + c) * G + iy) * G + ix;
        xo[c]     = bilin(covP, base, G, wx, wy);
        xo[3 + c] = bilin(varP, base, G, wx, wy);
    }
}

// ---------------- kernel 3: fused featbuild + tiled GEMM MLP ----------------
// Block: 256 threads (8 warps), tile = 256 pixels (row i of batch b) x 48 outputs.
// Warp tile: 6 outputs (uniform across lanes -> broadcast weight LDS) x 256 px.
// Lane tile: 4 stride-32 pixel-pairs x 6 outputs (24 f32x2 accumulators).
// smem layout (bytes):
//   x_s   [24][260] f  @ 0       (24960)   (reused as layer-3 reduction buffer)
//   h_s   [48][260] f  @ 24960   (49920)
//   w1d   [24][48] ull @ 74880   (9216)
//   w2d   [48][48] ull @ 84096   (18432)
//   w3d   [3][48]  ull @ 102528  (1152)
//   b1d   [48]     ull @ 103680  (384)
//   b2d   [48]     ull @ 104064  (384)
#define GEMM_SMEM 104448
#define XS_STRIDE 260

__global__ __launch_bounds__(256, 2) void gemm_kernel(
    const float* __restrict__ w1, const float* __restrict__ g1, const float* __restrict__ b1,
    const float* __restrict__ rm1, const float* __restrict__ rv1,
    const float* __restrict__ w2, const float* __restrict__ g2, const float* __restrict__ b2,
    const float* __restrict__ rm2, const float* __restrict__ rv2,
    const float* __restrict__ w3) {

    extern __shared__ __align__(16) char smem_raw[];
    float* x_s = (float*)smem_raw;
    float* h_s = (float*)(smem_raw + 24960);
    ull* w1d = (ull*)(smem_raw + 74880);
    ull* w2d = (ull*)(smem_raw + 84096);
    ull* w3d = (ull*)(smem_raw + 102528);
    ull* b1d = (ull*)(smem_raw + 103680);
    ull* b2d = (ull*)(smem_raw + 104064);

    const int t = threadIdx.x;
    const int i = blockIdx.x;   // row
    const int b = blockIdx.y;   // batch

    // ---- weight prep (folded BN, duplicated), spread over all 256 threads ----
    for (int e = t; e < 48 * 24; e += 256) {
        int o = e / 24, c = e - o * 24;
        float inv1 = g1[o] * rsqrtf(rv1[o] + 1e-5f);
        float w = w1[e] * inv1;
        w1d[c * 48 + o] = pack2(w, w);
    }
    for (int e = t; e < 48 * 48; e += 256) {
        int o = e / 48, c = e - o * 48;
        float inv2 = g2[o] * rsqrtf(rv2[o] + 1e-5f);
        float w = w2[e] * inv2;
        w2d[c * 48 + o] = pack2(w, w);
    }
    if (t < 48) {
        float inv1 = g1[t] * rsqrtf(rv1[t] + 1e-5f);
        float bb1 = fmaf(-rm1[t], inv1, b1[t]);
        b1d[t] = pack2(bb1, bb1);
        float inv2 = g2[t] * rsqrtf(rv2[t] + 1e-5f);
        float bb2 = fmaf(-rm2[t], inv2, b2[t]);
        b2d[t] = pack2(bb2, bb2);
        #pragma unroll
        for (int cc = 0; cc < 3; ++cc) {
            float w = w3[cc * 48 + t];
            w3d[cc * 48 + t] = pack2(w, w);
        }
    }

    // ---- feature build phase: thread t = pixel (i, j=t) ----
    {
        float x[24];
        if (t < 255) {
            const int j = t;
            #pragma unroll
            for (int c = 0; c < 3; ++c) {
                int off = (b * 3 + c) * G0 * G0 + i * G0 + j;
                float sg  = dS0[0][off] * (1.f/64.f);
                float ss  = dS0[1][off] * (1.f/64.f);
                float sgg = dS0[2][off] * (1.f/64.f);
                float sgs = dS0[3][off] * (1.f/64.f);
                x[c]     = fmaf(-sg, ss, sgs);
                x[3 + c] = fmaf(-sg, sg, sgg);
            }
            sampleLevel(dF1[0], dF1[1], G1, b, i, j, &x[6]);
            sampleLevel(dF2[0], dF2[1], G2, b, i, j, &x[12]);
            sampleLevel(dF3[0], dF3[1], G3, b, i, j, &x[18]);
        } else {
            #pragma unroll
            for (int f = 0; f < 24; ++f) x[f] = 0.f;
        }
        #pragma unroll
        for (int f = 0; f < 24; ++f)
            x_s[f * XS_STRIDE + t] = x[f];
    }
    __syncthreads();

    const int warp = t >> 5;
    const int lane = t & 31;
    const int o0   = warp * 6;          // 6 outputs per warp, uniform across lanes

    // lane owns pixel-pairs {lane, lane+32, lane+64, lane+96}

    // ---- layer 1: 24 -> 48 ----
    ull acc[24];                         // [k(out)][q(pair)]
    #pragma unroll
    for (int k = 0; k < 6; ++k) {
        ull bias = b1d[o0 + k];
        acc[k*4+0] = bias; acc[k*4+1] = bias; acc[k*4+2] = bias; acc[k*4+3] = bias;
    }
    #pragma unroll
    for (int c = 0; c < 24; ++c) {
        const float* xr = &x_s[c * XS_STRIDE];
        ull x0 = *(const ull*)(xr + 2 * lane);
        ull x1 = *(const ull*)(xr + 2 * (lane + 32));
        ull x2 = *(const ull*)(xr + 2 * (lane + 64));
        ull x3 = *(const ull*)(xr + 2 * (lane + 96));
        const ulonglong2* wr = (const ulonglong2*)&w1d[c * 48 + o0];
        ulonglong2 w01 = wr[0], w23 = wr[1], w45 = wr[2];
        ull wv[6] = {w01.x, w01.y, w23.x, w23.y, w45.x, w45.y};
        #pragma unroll
        for (int k = 0; k < 6; ++k) {
            acc[k*4+0] = fma2(wv[k], x0, acc[k*4+0]);
            acc[k*4+1] = fma2(wv[k], x1, acc[k*4+1]);
            acc[k*4+2] = fma2(wv[k], x2, acc[k*4+2]);
            acc[k*4+3] = fma2(wv[k], x3, acc[k*4+3]);
        }
    }
    // relu + store h (conflict-free STS.64)
    #pragma unroll
    for (int k = 0; k < 6; ++k) {
        float* hr = &h_s[(o0 + k) * XS_STRIDE];
        *(ull*)(hr + 2 * lane)        = relu2(acc[k*4+0]);
        *(ull*)(hr + 2 * (lane + 32)) = relu2(acc[k*4+1]);
        *(ull*)(hr + 2 * (lane + 64)) = relu2(acc[k*4+2]);
        *(ull*)(hr + 2 * (lane + 96)) = relu2(acc[k*4+3]);
    }
    __syncthreads();

    // ---- layer 2: 48 -> 48 ----
    #pragma unroll
    for (int k = 0; k < 6; ++k) {
        ull bias = b2d[o0 + k];
        acc[k*4+0] = bias; acc[k*4+1] = bias; acc[k*4+2] = bias; acc[k*4+3] = bias;
    }
    #pragma unroll
    for (int c = 0; c < 48; ++c) {
        const float* xr = &h_s[c * XS_STRIDE];
        ull x0 = *(const ull*)(xr + 2 * lane);
        ull x1 = *(const ull*)(xr + 2 * (lane + 32));
        ull x2 = *(const ull*)(xr + 2 * (lane + 64));
        ull x3 = *(const ull*)(xr + 2 * (lane + 96));
        const ulonglong2* wr = (const ulonglong2*)&w2d[c * 48 + o0];
        ulonglong2 w01 = wr[0], w23 = wr[1], w45 = wr[2];
        ull wv[6] = {w01.x, w01.y, w23.x, w23.y, w45.x, w45.y};
        #pragma unroll
        for (int k = 0; k < 6; ++k) {
            acc[k*4+0] = fma2(wv[k], x0, acc[k*4+0]);
            acc[k*4+1] = fma2(wv[k], x1, acc[k*4+1]);
            acc[k*4+2] = fma2(wv[k], x2, acc[k*4+2]);
            acc[k*4+3] = fma2(wv[k], x3, acc[k*4+3]);
        }
    }
    // ---- layer 3 folded: relu(h2) -> 3 partial accumulators over warp's 6 channels ----
    ull a3[12];                    // [cc][q]
    #pragma unroll
    for (int m = 0; m < 12; ++m) a3[m] = 0ull;
    #pragma unroll
    for (int k = 0; k < 6; ++k) {
        ull r0 = relu2(acc[k*4+0]);
        ull r1 = relu2(acc[k*4+1]);
        ull r2 = relu2(acc[k*4+2]);
        ull r3 = relu2(acc[k*4+3]);
        #pragma unroll
        for (int cc = 0; cc < 3; ++cc) {
            ull w = w3d[cc * 48 + o0 + k];     // uniform LDS.64
            a3[cc*4+0] = fma2(w, r0, a3[cc*4+0]);
            a3[cc*4+1] = fma2(w, r1, a3[cc*4+1]);
            a3[cc*4+2] = fma2(w, r2, a3[cc*4+2]);
            a3[cc*4+3] = fma2(w, r3, a3[cc*4+3]);
        }
    }

    // ---- cross-warp reduction via smem (reuse x_s; safe: last read before h-store sync) ----
    // layout: red[warp][cc*128 + pair]  (8 * 384 ull = 24576 B <= 24960)
    ull* red = (ull*)x_s;
    {
        ull* rw = red + warp * 384;
        #pragma unroll
        for (int cc = 0; cc < 3; ++cc) {
            rw[cc * 128 + lane]      = a3[cc*4+0];
            rw[cc * 128 + lane + 32] = a3[cc*4+1];
            rw[cc * 128 + lane + 64] = a3[cc*4+2];
            rw[cc * 128 + lane + 96] = a3[cc*4+3];
        }
    }
    __syncthreads();

    // 384 items (3 cc x 128 pairs) over 256 threads
    for (int item = t; item < 384; item += 256) {
        int cc = item >> 7;
        int p  = item & 127;
        ull s = red[item];
        #pragma unroll
        for (int w = 1; w < 8; ++w) s = add2(s, red[w * 384 + item]);
        float2 A = unpack2(s);
        int plane = (b * 3 + cc) * G0 * G0 + i * G0;
        int j0 = 2 * p;
        {
            float mx = dS0[0][plane + j0] * (1.f/64.f);
            float my = dS0[1][plane + j0] * (1.f/64.f);
            dAf[plane + j0] = A.x;
            dCf[plane + j0] = fmaf(-A.x, mx, my);
        }
        if (j0 + 1 < G0) {
            float mx = dS0[0][plane + j0 + 1] * (1.f/64.f);
            float my = dS0[1][plane + j0 + 1] * (1.f/64.f);
            dAf[plane + j0 + 1] = A.y;
            dCf[plane + j0 + 1] = fmaf(-A.y, mx, my);
        }
    }
}

// ---------------- kernel 4: upsample A,b + affine ----------------
__global__ __launch_bounds__(256) void final_kernel(const float* __restrict__ guide,
                                                    float* __restrict__ out) {
    __shared__ float sA[256];
    __shared__ float sC[256];
    const int y  = blockIdx.x;
    const int bc = blockIdx.y;
    const int t  = threadIdx.x;
    const float scale = (float)(254.0 / 1023.0);

    float py = y * scale;
    int iy = (int)py; if (iy > 253) iy = 253;
    float wy = py - iy;

    if (t < 255) {
        int b0 = bc * G0 * G0 + iy * G0 + t;
        float a0 = dAf[b0], a1 = dAf[b0 + G0];
        sA[t] = a0 + wy * (a1 - a0);
        float c0 = dCf[b0], c1 = dCf[b0 + G0];
        sC[t] = c0 + wy * (c1 - c0);
    }
    __syncthreads();

    size_t rowoff = ((size_t)bc * HH + y) * WW;
    float4 g = ((const float4*)(guide + rowoff))[t];
    float gv[4] = {g.x, g.y, g.z, g.w};
    float rv[4];
    #pragma unroll
    for (int k = 0; k < 4; ++k) {
        int xpix = 4 * t + k;
        float px = xpix * scale;
        int ix = (int)px; if (ix > 253) ix = 253;
        float wx = px - ix;
        float Av = sA[ix] + wx * (sA[ix + 1] - sA[ix]);
        float Cv = sC[ix] + wx * (sC[ix + 1] - sC[ix]);
        rv[k] = fmaf(Av, gv[k], Cv);
    }
    float4 r = {rv[0], rv[1], rv[2], rv[3]};
    ((float4*)(out + rowoff))[t] = r;
}

// ---------------- launch ----------------
extern "C" void kernel_launch(void* const* d_in, const int* in_sizes, int n_in,
                              void* d_out, int out_size) {
    const float* guide = (const float*)d_in[0];
    const float* src   = (const float*)d_in[1];
    const float* w1  = (const float*)d_in[2];
    const float* g1  = (const float*)d_in[3];
    const float* b1  = (const float*)d_in[4];
    const float* rm1 = (const float*)d_in[5];
    const float* rv1 = (const float*)d_in[6];
    const float* w2  = (const float*)d_in[7];
    const float* g2  = (const float*)d_in[8];
    const float* b2  = (const float*)d_in[9];
    const float* rm2 = (const float*)d_in[10];
    const float* rv2 = (const float*)d_in[11];
    const float* w3  = (const float*)d_in[12];
    float* out = (float*)d_out;

    cudaFuncSetAttribute(gemm_kernel, cudaFuncAttributeMaxDynamicSharedMemorySize, GEMM_SMEM);

    boxsum_kernel<<<dim3(32, NBC), 256>>>(guide, src);
    pyr1_kernel<<<dim3((G1*G1 + 255) / 256, NBC), 256>>>();
    pyr23_kernel<<<NBC, 256>>>();
    gemm_kernel<<<dim3(G0, BB), 256, GEMM_SMEM>>>(w1, g1, b1, rm1, rv1, w2, g2, b2, rm2, rv2, w3);
    final_kernel<<<dim3(HH, NBC), 256>>>(guide, out);
}